// round 16
// baseline (speedup 1.0000x reference)
#include <cuda_runtime.h>
#include <cstdint>

// MinArchitecture scan, 1 row/thread, cp.async pipeline, u-space recurrence:
//   t = tanh(u)                       [1 MUFU]
//   s = E(t^2) + t*O(t^2)             [deg-8 runtime Chebyshev fit, even/odd split]
//   u' = s*u + (xs_t - xs_{t+1})      [xs = d0*x]
// out = (xs_511 + s_511*u_511)/d0
// __launch_bounds__(64, 7): reg budget 146 so ptxas keeps the 9 coefficients
// and pipeline state resident (R15 regressed from coefficient demotion at 31 regs).

#define SEQ     512
#define BLOCK   64
#define PITCH   36           // floats/thread in smem (16x36B stride -> conflict-free LDS.128)
#define NCHUNK  (SEQ / 16)   // 32
#define QDEG    8            // poly degree (9 coeffs)

__device__ __forceinline__ float tanh_fast(float x) {
    float y;
    asm("tanh.approx.f32 %0, %1;" : "=f"(y) : "f"(x));
    return y;
}

__global__ void __launch_bounds__(BLOCK, 7) rnn_scan_kernel(
    const float* __restrict__ X,
    const float* __restrict__ W1,
    const float* __restrict__ W2,
    const float* __restrict__ bias,
    const float* __restrict__ Wz,
    const float* __restrict__ Ws,
    float* __restrict__ out)
{
    __shared__ float sbuf[BLOCK * PITCH];
    __shared__ float sf[64];             // fit scratch: node values
    __shared__ float sa[QDEG + 1];       // Chebyshev coeffs
    __shared__ float sq[QDEG + 1];       // monomial coeffs

    const int lt = threadIdx.x;
    const int r  = blockIdx.x * BLOCK + lt;

    // ----- uniform scalar constants -----
    const float a1 = 1.0f / (1.0f + expf(W1[1] - W1[0]));
    const float a2 = 1.0f / (1.0f + expf(W2[1] - W2[0]));
    float d0 = a1 - a2;
    if (fabsf(d0) < 1e-20f) d0 = 1e-20f;      // u-space exactly linear in d0
    const float rec = 1.0f / d0;
    const float wz = Wz[0];
    const float ws = Ws[0];
    const float b  = bias[0];
    const float c0 = 0.5f * (b + wz);
    const float c1 = 0.5f * ws;
    const float c2 = -wz;

    // ----- runtime Chebyshev fit of s(t) = 0.5+0.5*tanh(c0+c1*t+c2*t^2) on [-1,1] -----
    {
        const float PI = 3.14159265358979323846f;
        float th = PI * ((float)lt + 0.5f) / 64.0f;
        float t  = cosf(th);
        float y  = c0 + (c1 + c2 * t) * t;
        sf[lt] = 0.5f + 0.5f * tanhf(y);
        __syncthreads();
        if (lt <= QDEG) {
            float acc = 0.0f;
            for (int j = 0; j < 64; ++j) {
                float thj = PI * ((float)j + 0.5f) / 64.0f;
                acc += sf[j] * cosf((float)lt * thj);
            }
            sa[lt] = acc * ((lt == 0) ? (1.0f / 64.0f) : (2.0f / 64.0f));
        }
        __syncthreads();
        // Chebyshev -> monomial via shuffle-parallel T_k recurrence (warp 0)
        if (lt < 32) {
            int lane = lt;
            float prev = (lane == 0) ? 1.0f : 0.0f;   // T0
            float cur  = (lane == 1) ? 1.0f : 0.0f;   // T1
            float m = sa[0] * prev + sa[1] * cur;
            #pragma unroll
            for (int k = 2; k <= QDEG; ++k) {
                float up = __shfl_up_sync(0xffffffffu, cur, 1);
                if (lane == 0) up = 0.0f;
                float nxt = 2.0f * up - prev;
                prev = cur; cur = nxt;
                m = fmaf(sa[k], cur, m);
            }
            if (lane <= QDEG) sq[lane] = m;
        }
        __syncthreads();
    }

    // even/odd coefficient registers
    const float q0 = sq[0], q1 = sq[1], q2 = sq[2], q3 = sq[3], q4 = sq[4],
                q5 = sq[5], q6 = sq[6], q7 = sq[7], q8 = sq[8];

    // ----- cp.async pipeline (R7 skeleton) -----
    const float* row = X + (size_t)r * SEQ;
    float* my = sbuf + lt * PITCH;            // [0..15] = A, [16..31] = B

    uint32_t sb;
    {
        uint64_t tmp;
        asm("cvta.to.shared.u64 %0, %1;" : "=l"(tmp) : "l"(my));
        sb = (uint32_t)tmp;
    }

#define ISSUE(half, c) do {                                                  \
        _Pragma("unroll")                                                    \
        for (int j = 0; j < 4; ++j) {                                        \
            asm volatile("cp.async.cg.shared.global [%0], [%1], 16;"         \
                         :: "r"(sb + (unsigned)(((half) * 16 + j * 4) * 4)), \
                            "l"(row + (c) * 16 + j * 4) : "memory");         \
        }                                                                    \
        asm volatile("cp.async.commit_group;" ::: "memory");                 \
    } while (0)
#define WAIT1() asm volatile("cp.async.wait_group 1;" ::: "memory")
#define WAIT0() asm volatile("cp.async.wait_group 0;" ::: "memory")

    float uv = 0.0f;     // u state
    float xsprev;        // d0 * x_t (previous element, scaled)

    // gate: s = E(t2) + t*O(t2); chain tanh(50)->t2(4)->E(16)->s(4)
#define GATE(sv) do {                                          \
        float t  = tanh_fast(uv);                              \
        float t2 = t * t;                                      \
        float E  = fmaf(fmaf(fmaf(fmaf(q8, t2, q6), t2, q4),   \
                             t2, q2), t2, q0);                 \
        float O  = fmaf(fmaf(fmaf(q7, t2, q5), t2, q3), t2, q1); \
        sv = fmaf(t, O, E);                                    \
    } while (0)

    // one scan step consuming raw element XF (= x_{t+1})
#define STEP(XF) do {                                          \
        float xscur = d0 * (XF);                               \
        float s;                                               \
        GATE(s);                                               \
        uv = fmaf(s, uv, xsprev - xscur);                      \
        xsprev = xscur;                                        \
    } while (0)

#define PROC(half, E0) do {                                                 \
        _Pragma("unroll")                                                   \
        for (int q = 0; q < 4; ++q) {                                       \
            float4 v = *reinterpret_cast<const float4*>(my + (half) * 16 + q * 4); \
            if (q > 0 || (E0) <= 0) STEP(v.x);                              \
            if (q > 0 || (E0) <= 1) STEP(v.y);                              \
            if (q > 0 || (E0) <= 2) STEP(v.z);                              \
            STEP(v.w);                                                      \
        }                                                                   \
    } while (0)

    ISSUE(0, 0);
    ISSUE(1, 1);

    WAIT1();                       // chunk 0 resident
    xsprev = d0 * my[0];           // xs_0; uv = 0 seeds u_1 on first STEP
    PROC(0, 1);                    // consume x_1 .. x_15

    #pragma unroll 1
    for (int c = 2; c < NCHUNK; c += 2) {
        ISSUE(0, c);               // prefetch chunk c -> A
        WAIT1();                   // chunk c-1 (B) resident
        PROC(1, 0);
        ISSUE(1, c + 1);           // prefetch chunk c+1 -> B (max 31)
        WAIT1();                   // chunk c (A) resident
        PROC(0, 0);
    }

    WAIT0();
    PROC(1, 0);                    // chunk 31: consume .. x_511

    // final gate: out = (xs_511 + s_511*u_511)/d0
    {
        float s;
        GATE(s);
        out[r] = rec * fmaf(s, uv, xsprev);
    }
}

extern "C" void kernel_launch(void* const* d_in, const int* in_sizes, int n_in,
                              void* d_out, int out_size)
{
    const float* X    = (const float*)d_in[0];
    const float* W1   = (const float*)d_in[1];
    const float* W2   = (const float*)d_in[2];
    const float* bias = (const float*)d_in[3];
    const float* Wz   = (const float*)d_in[4];
    const float* Ws   = (const float*)d_in[5];
    float* out = (float*)d_out;

    const int batch = out_size;                    // 65536
    const int grid  = (batch + BLOCK - 1) / BLOCK; // 1024
    rnn_scan_kernel<<<grid, BLOCK>>>(X, W1, W2, bias, Wz, Ws, out);
}